// round 6
// baseline (speedup 1.0000x reference)
#include <cuda_runtime.h>
#include <math.h>

// Problem constants
#define Bq   4
#define Nq   1024
#define Cq   512
#define Hq   8
#define HDq  64
#define BHq  32
#define Mq   4096
#define SCALEq 0.125f
#define LN_EPSq 1e-5f

typedef unsigned long long u64;
typedef ulonglong2 u64x2;

// packed fp32x2 FMA (sm_103a). ptxas never emits this from C++.
__device__ __forceinline__ u64 f2fma(u64 a, u64 b, u64 c) {
    u64 d;
    asm("fma.rn.f32x2 %0, %1, %2, %3;" : "=l"(d) : "l"(a), "l"(b), "l"(c));
    return d;
}
__device__ __forceinline__ float2 upk(u64 v) {
    float2 r;
    asm("mov.b64 {%0, %1}, %2;" : "=f"(r.x), "=f"(r.y) : "l"(v));
    return r;
}
__device__ __forceinline__ u64 dup2(float x) {
    u64 r;
    asm("mov.b64 %0, {%1, %1};" : "=l"(r) : "f"(x));
    return r;
}

// Scratch (device globals — allocation-free)
__device__ float g_q   [BHq * Nq * HDq];    // [bh][n][d]
__device__ float g_k   [BHq * Nq * HDq];
__device__ float g_v   [BHq * Nq * HDq];
__device__ float g_aoP [4 * Mq * Cq];       // 4 k-split partials of attn-out
__device__ float g_yp  [Mq * Cq];           // pre-layernorm y
__device__ float g_pmax[BHq * Nq * 8];      // per-(row, col-tile) max
__device__ float g_psum[BHq * Nq * 8];      // per-(row, col-tile) sum exp

// ---------------------------------------------------------------------------
// Kernel 1: QKV GEMM. x[4096,512] @ Wqkv[512,1536] + bqkv -> scatter q/k/v
// 128x128x8 tiles, 256 threads, 8x8/thread, double-buffered, FFMA2 inner.
// ---------------------------------------------------------------------------
__global__ __launch_bounds__(256) void k_qkv(const float* __restrict__ A,
                                             const float* __restrict__ Bm,
                                             const float* __restrict__ bias) {
    const int K = 512, Nn = 1536;
    __shared__ float As[2][8][128];
    __shared__ float Bs[2][8][128];
    int tid = threadIdx.x;
    int bx = blockIdx.x, by = blockIdx.y;
    int aRow = tid >> 1, aCol = (tid & 1) << 2;
    int bRow = tid >> 5, bCol = (tid & 31) << 2;
    int ty = tid >> 4, tx = tid & 15;

    u64 acc[8][4];
#pragma unroll
    for (int i = 0; i < 8; i++)
#pragma unroll
        for (int j = 0; j < 4; j++) acc[i][j] = 0ULL;

    const float* Ap = A + (size_t)(by * 128 + aRow) * K + aCol;
    const float* Bp = Bm + (size_t)bRow * Nn + bx * 128 + bCol;

    {
        float4 av = *(const float4*)(Ap);
        As[0][aCol + 0][aRow] = av.x;
        As[0][aCol + 1][aRow] = av.y;
        As[0][aCol + 2][aRow] = av.z;
        As[0][aCol + 3][aRow] = av.w;
        *(float4*)&Bs[0][bRow][bCol] = *(const float4*)(Bp);
    }
    __syncthreads();

    for (int k0 = 0; k0 < K; k0 += 8) {
        int buf = (k0 >> 3) & 1;
        float4 av, bv;
        bool more = (k0 + 8) < K;
        if (more) {
            av = *(const float4*)(Ap + k0 + 8);
            bv = *(const float4*)(Bp + (size_t)(k0 + 8) * Nn);
        }
#pragma unroll
        for (int k = 0; k < 8; k++) {
            float a[8];
            *(float4*)&a[0] = *(const float4*)&As[buf][k][ty * 8];
            *(float4*)&a[4] = *(const float4*)&As[buf][k][ty * 8 + 4];
            u64x2 b0 = *(const u64x2*)&Bs[buf][k][tx * 8];
            u64x2 b1 = *(const u64x2*)&Bs[buf][k][tx * 8 + 4];
            u64 bp[4] = {b0.x, b0.y, b1.x, b1.y};
#pragma unroll
            for (int i = 0; i < 8; i++) {
                u64 ad = dup2(a[i]);
#pragma unroll
                for (int j = 0; j < 4; j++) acc[i][j] = f2fma(ad, bp[j], acc[i][j]);
            }
        }
        if (more) {
            int nb = buf ^ 1;
            As[nb][aCol + 0][aRow] = av.x;
            As[nb][aCol + 1][aRow] = av.y;
            As[nb][aCol + 2][aRow] = av.z;
            As[nb][aCol + 3][aRow] = av.w;
            *(float4*)&Bs[nb][bRow][bCol] = bv;
        }
        __syncthreads();
    }

#pragma unroll
    for (int i = 0; i < 8; i++) {
        int r = by * 128 + ty * 8 + i;
        int bb = r >> 10, n = r & 1023;
#pragma unroll
        for (int jp = 0; jp < 4; jp++) {
            float2 v2 = upk(acc[i][jp]);
            float vv[2] = {v2.x, v2.y};
#pragma unroll
            for (int l = 0; l < 2; l++) {
                int c = bx * 128 + tx * 8 + jp * 2 + l;
                float v = vv[l] + bias[c];
                int sel = c >> 9;
                int rem = c & 511;
                int h = rem >> 6, d = rem & 63;
                float* dst = (sel == 0) ? g_q : ((sel == 1) ? g_k : g_v);
                dst[((bb * 8 + h) * 1024 + n) * 64 + d] = v;
            }
        }
    }
}

// ---------------------------------------------------------------------------
// Kernel 2: scores. S = poly(ow; q·k^T*SCALE) pre-softmax into attn,
// plus per-(row, tile) softmax partials (max, sum exp) for fused softmax.
// 128x128 tile per block per bh, 256 threads, 8x8/thread, FFMA2 inner.
// ---------------------------------------------------------------------------
#define QKSTR 132
__global__ __launch_bounds__(256) void k_scores(const float* __restrict__ ow_in,
                                                float* __restrict__ attn) {
    extern __shared__ float sm[];
    float* Qt = sm;                // [d][row]
    float* Kt = sm + 64 * QKSTR;   // [d][col]
    int bh = blockIdx.z;
    int mb = blockIdx.y * 128;
    int nb = blockIdx.x * 128;
    int tid = threadIdx.x;

    {
        int row = tid >> 1;
        int d0 = (tid & 1) << 5;
        const float* qp = g_q + (size_t)(bh * 1024 + mb + row) * 64 + d0;
        const float* kp = g_k + (size_t)(bh * 1024 + nb + row) * 64 + d0;
#pragma unroll
        for (int m = 0; m < 8; m++) {
            int d = d0 + m * 4;
            float4 qv = *(const float4*)(qp + m * 4);
            Qt[(d + 0) * QKSTR + row] = qv.x;
            Qt[(d + 1) * QKSTR + row] = qv.y;
            Qt[(d + 2) * QKSTR + row] = qv.z;
            Qt[(d + 3) * QKSTR + row] = qv.w;
            float4 kv = *(const float4*)(kp + m * 4);
            Kt[(d + 0) * QKSTR + row] = kv.x;
            Kt[(d + 1) * QKSTR + row] = kv.y;
            Kt[(d + 2) * QKSTR + row] = kv.z;
            Kt[(d + 3) * QKSTR + row] = kv.w;
        }
    }
    __syncthreads();

    int ty = tid >> 4, tx = tid & 15;
    u64 acc[8][4];
#pragma unroll
    for (int i = 0; i < 8; i++)
#pragma unroll
        for (int j = 0; j < 4; j++) acc[i][j] = 0ULL;

#pragma unroll 8
    for (int d = 0; d < 64; d++) {
        float a[8];
        *(float4*)&a[0] = *(const float4*)(Qt + d * QKSTR + ty * 8);
        *(float4*)&a[4] = *(const float4*)(Qt + d * QKSTR + ty * 8 + 4);
        u64x2 b0 = *(const u64x2*)(Kt + d * QKSTR + tx * 8);
        u64x2 b1 = *(const u64x2*)(Kt + d * QKSTR + tx * 8 + 4);
        u64 bp[4] = {b0.x, b0.y, b1.x, b1.y};
#pragma unroll
        for (int i = 0; i < 8; i++) {
            u64 ad = dup2(a[i]);
#pragma unroll
            for (int j = 0; j < 4; j++) acc[i][j] = f2fma(ad, bp[j], acc[i][j]);
        }
    }

    float w0 = ow_in[0], w1 = ow_in[1], w2 = ow_in[2];
    float mw = fmaxf(w0, fmaxf(w1, w2));
    float e0 = __expf(w0 - mw), e1 = __expf(w1 - mw), e2 = __expf(w2 - mw);
    float inv = 1.f / (e0 + e1 + e2);
    w0 = e0 * inv; w1 = e1 * inv; w2 = e2 * inv;

#pragma unroll
    for (int i = 0; i < 8; i++) {
        int row = bh * 1024 + mb + ty * 8 + i;
        float o[8];
#pragma unroll
        for (int jp = 0; jp < 4; jp++) {
            float2 v2 = upk(acc[i][jp]);
            float s;
            s = v2.x * SCALEq; o[jp * 2 + 0] = s * (w0 + s * (w1 + s * w2));
            s = v2.y * SCALEq; o[jp * 2 + 1] = s * (w0 + s * (w1 + s * w2));
        }
        float* dst = attn + (size_t)row * 1024 + nb + tx * 8;
        *(float4*)dst = *(float4*)&o[0];
        *(float4*)(dst + 4) = *(float4*)&o[4];

        // softmax partials over this 128-col tile: reduce across tx (16 lanes
        // of a half-warp; lane = (ty&1)*16 + tx, xor offsets 1..8 stay in half)
        float lm = fmaxf(fmaxf(fmaxf(o[0], o[1]), fmaxf(o[2], o[3])),
                         fmaxf(fmaxf(o[4], o[5]), fmaxf(o[6], o[7])));
#pragma unroll
        for (int off = 8; off; off >>= 1)
            lm = fmaxf(lm, __shfl_xor_sync(0xffffffffu, lm, off));
        float ls = 0.f;
#pragma unroll
        for (int j = 0; j < 8; j++) ls += __expf(o[j] - lm);
#pragma unroll
        for (int off = 8; off; off >>= 1)
            ls += __shfl_xor_sync(0xffffffffu, ls, off);
        if (tx == 0) {
            g_pmax[(size_t)row * 8 + blockIdx.x] = lm;
            g_psum[(size_t)row * 8 + blockIdx.x] = ls;
        }
    }
}

// ---------------------------------------------------------------------------
// Kernel 3: fused softmax + partial AV. Per (b,h,z): rows [mb,mb+128),
// cols [z*256,(z+1)*256). Prologue builds global (M, 1/L) per row from the
// 8 scores partials; A staging applies e=exp(s-M)/L, writes FINAL attn in
// place (disjoint col ranges per z), and feeds e into the FFMA2 mainloop.
// ---------------------------------------------------------------------------
#define ATSTR 132
#define VSTR2 68
__global__ __launch_bounds__(256) void k_av(float* __restrict__ attn) {
    extern __shared__ float sm[];
    float* At = sm;                       // [k 0..63][row 0..127] transposed
    float* Vs = sm + 64 * ATSTR;          // [k][d]
    float* sM = sm + 64 * ATSTR + 64 * VSTR2;        // [128]
    float* sIL = sM + 128;                            // [128]
    int mb = blockIdx.x * 128;
    int bh = blockIdx.y;
    int kz = blockIdx.z << 8;             // z * 256
    int tid = threadIdx.x;
    int ty = tid >> 4, tx = tid & 15;

    // prologue: global row max + inverse sum from per-tile partials
    if (tid < 128) {
        size_t r = (size_t)(bh * 1024 + mb + tid);
        float4 m0 = *(const float4*)(g_pmax + r * 8);
        float4 m1 = *(const float4*)(g_pmax + r * 8 + 4);
        float M = fmaxf(fmaxf(fmaxf(m0.x, m0.y), fmaxf(m0.z, m0.w)),
                        fmaxf(fmaxf(m1.x, m1.y), fmaxf(m1.z, m1.w)));
        float4 s0 = *(const float4*)(g_psum + r * 8);
        float4 s1 = *(const float4*)(g_psum + r * 8 + 4);
        float L = s0.x * __expf(m0.x - M) + s0.y * __expf(m0.y - M)
                + s0.z * __expf(m0.z - M) + s0.w * __expf(m0.w - M)
                + s1.x * __expf(m1.x - M) + s1.y * __expf(m1.y - M)
                + s1.z * __expf(m1.z - M) + s1.w * __expf(m1.w - M);
        sM[tid] = M;
        sIL[tid] = 1.f / L;
    }
    __syncthreads();

    u64 acc[4][4];
#pragma unroll
    for (int i = 0; i < 4; i++)
#pragma unroll
        for (int j = 0; j < 4; j++) acc[i][j] = 0ULL;

    for (int k0 = 0; k0 < 256; k0 += 64) {
        {   // stage attn chunk: softmax-normalize, write back final, transpose
            int row = tid >> 1;
            int c0 = (tid & 1) << 5;
            float M = sM[row], il = sIL[row];
            float* ap = attn + (size_t)(bh * 1024 + mb + row) * 1024 + kz + k0 + c0;
#pragma unroll
            for (int m = 0; m < 8; m++) {
                float4 av = *(const float4*)(ap + m * 4);
                av.x = __expf(av.x - M) * il;
                av.y = __expf(av.y - M) * il;
                av.z = __expf(av.z - M) * il;
                av.w = __expf(av.w - M) * il;
                *(float4*)(ap + m * 4) = av;   // final attn output (in place)
                int kk = c0 + m * 4;
                At[(kk + 0) * ATSTR + row] = av.x;
                At[(kk + 1) * ATSTR + row] = av.y;
                At[(kk + 2) * ATSTR + row] = av.z;
                At[(kk + 3) * ATSTR + row] = av.w;
            }
        }
        {   // fill Vs natural: Vs[k][d]
            int vr = tid >> 2;
            int d0 = (tid & 3) << 4;
            const float* vp = g_v + (size_t)(bh * 1024 + kz + k0 + vr) * 64 + d0;
            float* vd = Vs + vr * VSTR2 + d0;
#pragma unroll
            for (int m = 0; m < 4; m++)
                *(float4*)(vd + m * 4) = *(const float4*)(vp + m * 4);
        }
        __syncthreads();

#pragma unroll 8
        for (int kk = 0; kk < 64; kk++) {
            u64x2 a01 = *(const u64x2*)(At + kk * ATSTR + ty * 8);      // rows 0-3
            u64x2 a23 = *(const u64x2*)(At + kk * ATSTR + ty * 8 + 4);  // rows 4-7
            float4 bf = *(const float4*)(Vs + kk * VSTR2 + tx * 4);
            u64 ap4[4] = {a01.x, a01.y, a23.x, a23.y};
            u64 bp4[4] = {dup2(bf.x), dup2(bf.y), dup2(bf.z), dup2(bf.w)};
#pragma unroll
            for (int i = 0; i < 4; i++)
#pragma unroll
                for (int j = 0; j < 4; j++) acc[i][j] = f2fma(ap4[i], bp4[j], acc[i][j]);
        }
        __syncthreads();
    }

    int b = bh >> 3, h = bh & 7;
    float* base = g_aoP + (size_t)blockIdx.z * (Mq * Cq);
#pragma unroll
    for (int p = 0; p < 4; p++) {
        float2 v0 = upk(acc[p][0]);
        float2 v1 = upk(acc[p][1]);
        float2 v2 = upk(acc[p][2]);
        float2 v3 = upk(acc[p][3]);
        float4 lo = {v0.x, v1.x, v2.x, v3.x};   // row 2p
        float4 hi = {v0.y, v1.y, v2.y, v3.y};   // row 2p+1
        int n0 = mb + ty * 8 + 2 * p;
        *(float4*)(base + (size_t)(b * 1024 + n0) * 512 + h * 64 + tx * 4) = lo;
        *(float4*)(base + (size_t)(b * 1024 + n0 + 1) * 512 + h * 64 + tx * 4) = hi;
    }
}

// ---------------------------------------------------------------------------
// Kernel 4: proj GEMM + bias + residual. A = sum of 4 g_aoP partials.
// 128x128x8 tiles, double-buffered, FFMA2 inner.
// ---------------------------------------------------------------------------
__global__ __launch_bounds__(256) void k_proj(const float* __restrict__ x,
                                              const float* __restrict__ Bm,
                                              const float* __restrict__ bias) {
    const int K = 512, Nn = 512;
    const int P = Mq * Cq;
    __shared__ float As[2][8][128];
    __shared__ float Bs[2][8][128];
    int tid = threadIdx.x;
    int bx = blockIdx.x, by = blockIdx.y;
    int aRow = tid >> 1, aCol = (tid & 1) << 2;
    int bRow = tid >> 5, bCol = (tid & 31) << 2;
    int ty = tid >> 4, tx = tid & 15;

    u64 acc[8][4];
#pragma unroll
    for (int i = 0; i < 8; i++)
#pragma unroll
        for (int j = 0; j < 4; j++) acc[i][j] = 0ULL;

    const float* Ap = g_aoP + (size_t)(by * 128 + aRow) * K + aCol;
    const float* Bp = Bm + (size_t)bRow * Nn + bx * 128 + bCol;

    {
        float4 a0 = *(const float4*)(Ap);
        float4 a1 = *(const float4*)(Ap + P);
        float4 a2 = *(const float4*)(Ap + 2 * P);
        float4 a3 = *(const float4*)(Ap + 3 * P);
        float4 av = {a0.x + a1.x + a2.x + a3.x, a0.y + a1.y + a2.y + a3.y,
                     a0.z + a1.z + a2.z + a3.z, a0.w + a1.w + a2.w + a3.w};
        As[0][aCol + 0][aRow] = av.x;
        As[0][aCol + 1][aRow] = av.y;
        As[0][aCol + 2][aRow] = av.z;
        As[0][aCol + 3][aRow] = av.w;
        *(float4*)&Bs[0][bRow][bCol] = *(const float4*)(Bp);
    }
    __syncthreads();

    for (int k0 = 0; k0 < K; k0 += 8) {
        int buf = (k0 >> 3) & 1;
        float4 av, bv;
        bool more = (k0 + 8) < K;
        if (more) {
            float4 a0 = *(const float4*)(Ap + k0 + 8);
            float4 a1 = *(const float4*)(Ap + P + k0 + 8);
            float4 a2 = *(const float4*)(Ap + 2 * P + k0 + 8);
            float4 a3 = *(const float4*)(Ap + 3 * P + k0 + 8);
            av.x = a0.x + a1.x + a2.x + a3.x;
            av.y = a0.y + a1.y + a2.y + a3.y;
            av.z = a0.z + a1.z + a2.z + a3.z;
            av.w = a0.w + a1.w + a2.w + a3.w;
            bv = *(const float4*)(Bp + (size_t)(k0 + 8) * Nn);
        }
#pragma unroll
        for (int k = 0; k < 8; k++) {
            float a[8];
            *(float4*)&a[0] = *(const float4*)&As[buf][k][ty * 8];
            *(float4*)&a[4] = *(const float4*)&As[buf][k][ty * 8 + 4];
            u64x2 b0 = *(const u64x2*)&Bs[buf][k][tx * 8];
            u64x2 b1 = *(const u64x2*)&Bs[buf][k][tx * 8 + 4];
            u64 bp[4] = {b0.x, b0.y, b1.x, b1.y};
#pragma unroll
            for (int i = 0; i < 8; i++) {
                u64 ad = dup2(a[i]);
#pragma unroll
                for (int j = 0; j < 4; j++) acc[i][j] = f2fma(ad, bp[j], acc[i][j]);
            }
        }
        if (more) {
            int nb2 = buf ^ 1;
            As[nb2][aCol + 0][aRow] = av.x;
            As[nb2][aCol + 1][aRow] = av.y;
            As[nb2][aCol + 2][aRow] = av.z;
            As[nb2][aCol + 3][aRow] = av.w;
            *(float4*)&Bs[nb2][bRow][bCol] = bv;
        }
        __syncthreads();
    }

#pragma unroll
    for (int i = 0; i < 8; i++) {
        int r = by * 128 + ty * 8 + i;
#pragma unroll
        for (int jp = 0; jp < 4; jp++) {
            float2 v2 = upk(acc[i][jp]);
            int c = bx * 128 + tx * 8 + jp * 2;
            g_yp[(size_t)r * 512 + c]     = v2.x + bias[c]     + x[(size_t)r * 512 + c];
            g_yp[(size_t)r * 512 + c + 1] = v2.y + bias[c + 1] + x[(size_t)r * 512 + c + 1];
        }
    }
}

// ---------------------------------------------------------------------------
// Kernel 5: LayerNorm over last dim (512), write y to d_out.
// ---------------------------------------------------------------------------
__global__ __launch_bounds__(128) void k_ln(const float* __restrict__ gamma,
                                            const float* __restrict__ beta,
                                            float* __restrict__ y) {
    __shared__ float s1[4], s2[4];
    int row = blockIdx.x;
    int tid = threadIdx.x;
    const float* p = g_yp + (size_t)row * 512;
    float4 v = *(const float4*)(p + tid * 4);

    float s = v.x + v.y + v.z + v.w;
    float ss = v.x * v.x + v.y * v.y + v.z * v.z + v.w * v.w;
#pragma unroll
    for (int o = 16; o; o >>= 1) {
        s += __shfl_xor_sync(0xffffffffu, s, o);
        ss += __shfl_xor_sync(0xffffffffu, ss, o);
    }
    int wid = tid >> 5, lane = tid & 31;
    if (lane == 0) { s1[wid] = s; s2[wid] = ss; }
    __syncthreads();
    if (tid == 0) {
        s1[0] = s1[0] + s1[1] + s1[2] + s1[3];
        s2[0] = s2[0] + s2[1] + s2[2] + s2[3];
    }
    __syncthreads();
    float mu = s1[0] * (1.f / 512.f);
    float var = s2[0] * (1.f / 512.f) - mu * mu;
    float rstd = rsqrtf(var + LN_EPSq);

    int c = tid * 4;
    float4 g = *(const float4*)(gamma + c);
    float4 be = *(const float4*)(beta + c);
    float4 o;
    o.x = (v.x - mu) * rstd * g.x + be.x;
    o.y = (v.y - mu) * rstd * g.y + be.y;
    o.z = (v.z - mu) * rstd * g.z + be.z;
    o.w = (v.w - mu) * rstd * g.w + be.w;
    *(float4*)(y + (size_t)row * 512 + c) = o;
}

// ---------------------------------------------------------------------------
extern "C" void kernel_launch(void* const* d_in, const int* in_sizes, int n_in,
                              void* d_out, int out_size) {
    (void)in_sizes; (void)n_in; (void)out_size;
    const float* x     = (const float*)d_in[0];
    const float* Wqkv  = (const float*)d_in[1];
    const float* bqkv  = (const float*)d_in[2];
    const float* ow    = (const float*)d_in[3];
    const float* Wproj = (const float*)d_in[4];
    const float* bproj = (const float*)d_in[5];
    const float* gamma = (const float*)d_in[6];
    const float* beta  = (const float*)d_in[7];

    float* out      = (float*)d_out;
    float* y_out    = out;                         // [4,1024,512]
    float* attn_out = out + (size_t)Bq * Nq * Cq;  // [4,8,1024,1024]

    int scores_smem = 2 * 64 * QKSTR * (int)sizeof(float);            // 67584 B
    int av_smem = (64 * ATSTR + 64 * VSTR2 + 256) * (int)sizeof(float); // 52224 B
    cudaFuncSetAttribute(k_scores, cudaFuncAttributeMaxDynamicSharedMemorySize,
                         scores_smem);
    cudaFuncSetAttribute(k_av, cudaFuncAttributeMaxDynamicSharedMemorySize,
                         av_smem);

    k_qkv   <<<dim3(12, 32), 256>>>(x, Wqkv, bqkv);
    k_scores<<<dim3(8, 8, 32), 256, scores_smem>>>(ow, attn_out);
    k_av    <<<dim3(8, 32, 4), 256, av_smem>>>(attn_out);
    k_proj  <<<dim3(4, 32), 256>>>(x, Wproj, bproj);
    k_ln    <<<4096, 128>>>(gamma, beta, y_out);
}